// round 14
// baseline (speedup 1.0000x reference)
#include <cuda_runtime.h>
#include <cuda_bf16.h>
#include <cstdint>

#define D 128
#define MAXNZ 512
#define BM 16              // batch rows per lin CTA
#define DN 32              // output cols per lin CTA
#define SWS 132            // smem W row stride (floats) -> conflict-free LDS.128
#define MAXB 4096
#define CH 4               // pipeline chunks

__device__ float g_agg[(size_t)MAXB * D];

// ---- persistent streams/events (created once at process start; no device
//      memory, identical launch sequence every kernel_launch call) ----------
static cudaStream_t g_s2 = nullptr;
static cudaEvent_t  g_evA[CH];     // agg(chunk) done
static cudaEvent_t  g_evL = nullptr; // all lin done
namespace {
struct StreamInit {
    StreamInit() {
        cudaStreamCreateWithFlags(&g_s2, cudaStreamNonBlocking);
        for (int i = 0; i < CH; ++i)
            cudaEventCreateWithFlags(&g_evA[i], cudaEventDisableTiming);
        cudaEventCreateWithFlags(&g_evL, cudaEventDisableTiming);
    }
};
static StreamInit g_stream_init;
}

// ---------------------------------------------------------------------------
// Kernel 1 (unchanged from 23.3us best): scan F[uid] + sparse aggregate vs E.
// ---------------------------------------------------------------------------
__global__ __launch_bounds__(128) void agg_kernel(
    const int* __restrict__ ids,
    const float* __restrict__ F,
    const float* __restrict__ E,
    int n_total,
    float* __restrict__ agg)
{
    __shared__ int   s_idx[MAXNZ];
    __shared__ float s_w[MAXNZ];
    __shared__ int   s_cnt;

    const int tid = threadIdx.x;
    if (tid == 0) s_cnt = 0;
    __syncthreads();

    const int uid = ids[blockIdx.x];
    const float* __restrict__ row = F + (size_t)uid * (size_t)n_total;

    if (((n_total & 3) == 0) && ((((uintptr_t)row) & 15) == 0)) {
        const float4* __restrict__ row4 = (const float4*)row;
        const int nvec = n_total >> 2;
        for (int i = tid; i < nvec; i += 128) {
            float4 v = __ldcs(&row4[i]);
            if (v.x != 0.0f) { int p = atomicAdd(&s_cnt, 1); if (p < MAXNZ) { s_idx[p] = 4*i + 0; s_w[p] = v.x; } }
            if (v.y != 0.0f) { int p = atomicAdd(&s_cnt, 1); if (p < MAXNZ) { s_idx[p] = 4*i + 1; s_w[p] = v.y; } }
            if (v.z != 0.0f) { int p = atomicAdd(&s_cnt, 1); if (p < MAXNZ) { s_idx[p] = 4*i + 2; s_w[p] = v.z; } }
            if (v.w != 0.0f) { int p = atomicAdd(&s_cnt, 1); if (p < MAXNZ) { s_idx[p] = 4*i + 3; s_w[p] = v.w; } }
        }
    } else {
        for (int i = tid; i < n_total; i += 128) {
            float v = __ldcs(&row[i]);
            if (v != 0.0f) { int p = atomicAdd(&s_cnt, 1); if (p < MAXNZ) { s_idx[p] = i; s_w[p] = v; } }
        }
    }
    __syncthreads();

    const int cnt = min(s_cnt, MAXNZ);
    const int d = tid;
    float acc = 0.0f;

    int j = 0;
    for (; j + 4 <= cnt; j += 4) {
        const float w0 = s_w[j + 0], w1 = s_w[j + 1], w2 = s_w[j + 2], w3 = s_w[j + 3];
        const float e0 = E[(size_t)s_idx[j + 0] * D + d];
        const float e1 = E[(size_t)s_idx[j + 1] * D + d];
        const float e2 = E[(size_t)s_idx[j + 2] * D + d];
        const float e3 = E[(size_t)s_idx[j + 3] * D + d];
        acc += w0 * e0;
        acc += w1 * e1;
        acc += w2 * e2;
        acc += w3 * e3;
    }
    for (; j < cnt; ++j)
        acc += s_w[j] * E[(size_t)s_idx[j] * D + d];

    agg[(size_t)blockIdx.x * D + d] = acc;
}

// ---------------------------------------------------------------------------
// Kernel 2 (unchanged structure): out = agg @ W^T + bias for one row chunk.
// agg/out pointers are pre-offset by the chunk base; nrows = chunk size.
// ---------------------------------------------------------------------------
__global__ __launch_bounds__(128) void lin_kernel(
    const float* __restrict__ agg,
    const float* __restrict__ W,
    const float* __restrict__ bias,
    float* __restrict__ out,
    int nrows)
{
    __shared__ __align__(16) float sW[DN * SWS];   // [32][132]
    __shared__ __align__(16) float sA[BM * D];     // [16][128]

    const int tid = threadIdx.x;
    const int tx  = tid & 31;
    const int ty  = tid >> 5;
    const int row0 = blockIdx.x * BM;
    const int d0   = blockIdx.y * DN;

    {
        const float4* __restrict__ W4 = (const float4*)W;
        float4* __restrict__ sW4 = (float4*)sW;
#pragma unroll
        for (int t = 0; t < 8; ++t) {
            const int i4  = tid + t * 128;     // 0..1023
            const int c   = i4 >> 5;
            const int k4c = i4 & 31;
            sW4[c * (SWS / 4) + k4c] = W4[(size_t)(d0 + c) * (D / 4) + k4c];
        }
    }
    {
        const float4* __restrict__ A4 = (const float4*)(agg + (size_t)row0 * D);
        float4* __restrict__ sA4 = (float4*)sA;
#pragma unroll
        for (int t = 0; t < 4; ++t) {
            const int i4 = tid + t * 128;
            const int r  = row0 + (i4 >> 5);
            sA4[i4] = (r < nrows) ? A4[i4] : make_float4(0.f, 0.f, 0.f, 0.f);
        }
    }
    __syncthreads();

    float acc[4] = {0.f, 0.f, 0.f, 0.f};
    const float4* __restrict__ a4 = (const float4*)sA;
    const float4* __restrict__ w4 = ((const float4*)sW) + tx * (SWS / 4);

#pragma unroll 8
    for (int k4 = 0; k4 < D / 4; ++k4) {
        const float4 w = w4[k4];                         // conflict-free
#pragma unroll
        for (int r = 0; r < 4; ++r) {
            const float4 a = a4[(4 * ty + r) * (D / 4) + k4];  // broadcast
            acc[r] += a.x * w.x;
            acc[r] += a.y * w.y;
            acc[r] += a.z * w.z;
            acc[r] += a.w * w.w;
        }
    }

    const float b = bias[d0 + tx];
#pragma unroll
    for (int r = 0; r < 4; ++r) {
        const int rr = row0 + 4 * ty + r;
        if (rr < nrows)
            out[(size_t)rr * D + d0 + tx] = acc[r] + b;
    }
}

extern "C" void kernel_launch(void* const* d_in, const int* in_sizes, int n_in,
                              void* d_out, int out_size)
{
    const int*   ids  = (const int*)  d_in[0];
    const float* F    = (const float*)d_in[1];
    const float* E    = (const float*)d_in[2];
    const float* W    = (const float*)d_in[3];
    const float* bias = (const float*)d_in[4];
    float* out = (float*)d_out;

    const int B       = in_sizes[0];
    const int n_total = in_sizes[2] / D;

    float* agg;
    cudaGetSymbolAddress((void**)&agg, g_agg);

    if (g_s2) {
        // ---- pipelined: agg chunks on stream 0, lin chunks on g_s2 ----
        const int chunk = (B + CH - 1) / CH;
        for (int c = 0; c < CH; ++c) {
            const int base  = c * chunk;
            if (base >= B) break;
            const int rows  = (base + chunk <= B) ? chunk : (B - base);

            agg_kernel<<<rows, 128>>>(ids + base, F, E, n_total,
                                      agg + (size_t)base * D);
            cudaEventRecord(g_evA[c], 0);
            cudaStreamWaitEvent(g_s2, g_evA[c], 0);

            dim3 grid2((rows + BM - 1) / BM, D / DN);
            lin_kernel<<<grid2, 128, 0, g_s2>>>(agg + (size_t)base * D, W, bias,
                                                out + (size_t)base * D, rows);
        }
        cudaEventRecord(g_evL, g_s2);
        cudaStreamWaitEvent(0, g_evL, 0);      // join fork before capture ends
    } else {
        // ---- fallback: sequential on default stream ----
        agg_kernel<<<B, 128>>>(ids, F, E, n_total, agg);
        dim3 grid2((B + BM - 1) / BM, D / DN);
        lin_kernel<<<grid2, 128>>>(agg, W, bias, out, B);
    }
}